// round 5
// baseline (speedup 1.0000x reference)
#include <cuda_runtime.h>
#include <cuda_bf16.h>

#define N_NODES_MAX 10000
#define E_MAX       320000
#define C           128
#define K2          256     // fused K: [agg | x]
#define STRIDE      192     // padded adjacency slots per node (deg mean 64, sd 8)

typedef unsigned long long ull;

// ---- device scratch ----
__device__ int   g_deg[N_NODES_MAX];
__device__ int   g_adj[N_NODES_MAX * STRIDE];
__device__ float g_agg[N_NODES_MAX * C];
// duplicated fused weights: g_w2[k*256 + 2c] = g_w2[k*256 + 2c+1] = W2[k][c]
// where W2[k][c] = (k<128) ? w[c][k] : b[c][k-128]
__device__ float g_w2[K2 * 2 * C];

// ---- packed fp32x2 helpers ----
__device__ __forceinline__ void upk(float& lo, float& hi, ull v) {
    asm("mov.b64 {%0, %1}, %2;" : "=f"(lo), "=f"(hi) : "l"(v));
}
__device__ __forceinline__ void fma2(ull& d, ull a, ull b) {
    asm("fma.rn.f32x2 %0, %1, %2, %0;" : "+l"(d) : "l"(a), "l"(b));
}

// ---------------------------------------------------------------------------
// 1) init: zero degree counters + build duplicated fused weight matrix
// ---------------------------------------------------------------------------
__global__ void k_init(const float* __restrict__ w,
                       const float* __restrict__ b, int n) {
    int idx = blockIdx.x * blockDim.x + threadIdx.x;   // 0..32767
    if (idx < n) g_deg[idx] = 0;
    if (idx < K2 * C) {
        int k = idx >> 7;          // 0..255
        int c = idx & (C - 1);     // 0..127
        float v = (k < C) ? w[c * C + k] : b[c * C + (k - C)];
        ((float2*)g_w2)[k * C + c] = make_float2(v, v);   // coalesced float2 store
    }
}

// ---------------------------------------------------------------------------
// 2) fill padded adjacency: edge (i,j) -> adj[i] += j, adj[j] += i
// ---------------------------------------------------------------------------
__global__ void k_fill(const int* __restrict__ ei, int e, int n) {
    int k = blockIdx.x * blockDim.x + threadIdx.x;
    if (k >= e) return;
    int2 p = ((const int2*)ei)[k];
    int i = p.x, j = p.y;
    if ((unsigned)i >= (unsigned)n || (unsigned)j >= (unsigned)n) return;
    int si = atomicAdd(&g_deg[i], 1);
    if (si < STRIDE) g_adj[i * STRIDE + si] = j;
    int sj = atomicAdd(&g_deg[j], 1);
    if (sj < STRIDE) g_adj[j * STRIDE + sj] = i;
}

// ---------------------------------------------------------------------------
// 3) mean aggregation: one warp per node, lane owns float4 (4 channels)
// ---------------------------------------------------------------------------
__global__ void k_agg(const float* __restrict__ x, int n) {
    int warp = (blockIdx.x * blockDim.x + threadIdx.x) >> 5;
    if (warp >= n) return;
    int lane = threadIdx.x & 31;
    int deg = g_deg[warp];
    int cnt = deg < STRIDE ? deg : STRIDE;
    const int* adj = &g_adj[warp * STRIDE];

    float4 a0 = make_float4(0.f, 0.f, 0.f, 0.f);
    float4 a1 = a0, a2 = a0, a3 = a0;

    const float4* x4 = (const float4*)x;
    int i = 0;
    for (; i + 3 < cnt; i += 4) {
        int m0 = adj[i], m1 = adj[i + 1], m2 = adj[i + 2], m3 = adj[i + 3];
        float4 v0 = x4[m0 * 32 + lane];
        float4 v1 = x4[m1 * 32 + lane];
        float4 v2 = x4[m2 * 32 + lane];
        float4 v3 = x4[m3 * 32 + lane];
        a0.x += v0.x; a0.y += v0.y; a0.z += v0.z; a0.w += v0.w;
        a1.x += v1.x; a1.y += v1.y; a1.z += v1.z; a1.w += v1.w;
        a2.x += v2.x; a2.y += v2.y; a2.z += v2.z; a2.w += v2.w;
        a3.x += v3.x; a3.y += v3.y; a3.z += v3.z; a3.w += v3.w;
    }
    for (; i < cnt; i++) {
        float4 v = x4[adj[i] * 32 + lane];
        a0.x += v.x; a0.y += v.y; a0.z += v.z; a0.w += v.w;
    }
    a0.x += a1.x + a2.x + a3.x;
    a0.y += a1.y + a2.y + a3.y;
    a0.z += a1.z + a2.z + a3.z;
    a0.w += a1.w + a2.w + a3.w;

    float inv = (deg > 0) ? 1.0f / (float)deg : 0.0f;
    ((float4*)g_agg)[warp * 32 + lane] =
        make_float4(a0.x * inv, a0.y * inv, a0.z * inv, a0.w * inv);
}

// ---------------------------------------------------------------------------
// 4) tiled fused SGEMM + ReLU, f32x2 datapath.
//    out = relu(A2 @ W2), M=10000, N=128, K=256 (A2 = [agg|x], W2 = [w;b]^T).
//    Tile: 32 nodes (M) x 64 channels (N half, blockIdx.y) per 128-thr block.
//    thread: ng = tid&3 -> 8 consecutive nodes (4 f32x2 pairs from LDS.128),
//            cg = tid>>2 -> 2 channels (1 LDG.128 of pre-duplicated weights,
//            128B unique per warp per k thanks to 4-lane broadcast).
//    Per warp per k: 1 LDG + 2 LDS + 8 FFMA2 (64 lane-FMAs).
// ---------------------------------------------------------------------------
#define MT 32
#define KC 64

__global__ void k_gemm(const float* __restrict__ x,
                       float* __restrict__ out, int n) {
    __shared__ float s_a[KC][MT];    // 8 KB, transposed activation chunk

    const int tid = threadIdx.x;     // 0..127
    const int m0  = blockIdx.x * MT;
    const int ng  = tid & 3;         // node group: nodes ng*8 .. ng*8+7
    const int cg  = tid >> 2;        // 0..31
    const int ch0 = blockIdx.y * 64 + cg * 2;   // 2 channels per thread

    ull acc[4][2];                    // [node pair][channel]
    #pragma unroll
    for (int p = 0; p < 4; p++) { acc[p][0] = 0ull; acc[p][1] = 0ull; }

    for (int kc = 0; kc < K2; kc += KC) {
        // ---- stage A2 chunk transposed: s_a[k][node] ----
        __syncthreads();
        const float* src = (kc < C) ? g_agg : x;
        const int koff = kc & (C - 1);
        #pragma unroll
        for (int r = 0; r < 4; r++) {
            int idx  = r * 128 + tid;        // 0..511
            int node = idx & (MT - 1);
            int kq   = idx >> 5;             // 0..15 -> k = kq*4
            int gn   = m0 + node;
            float4 v = make_float4(0.f, 0.f, 0.f, 0.f);
            if (gn < n) v = *(const float4*)&src[(size_t)gn * C + koff + kq * 4];
            s_a[kq * 4 + 0][node] = v.x;
            s_a[kq * 4 + 1][node] = v.y;
            s_a[kq * 4 + 2][node] = v.z;
            s_a[kq * 4 + 3][node] = v.w;
        }
        __syncthreads();

        const float* wbase = g_w2 + (size_t)kc * (2 * C) + 2 * ch0;
        #pragma unroll 4
        for (int k = 0; k < KC; k++) {
            ulonglong2 wd = __ldg((const ulonglong2*)(wbase + (size_t)k * (2 * C)));
            const ulonglong2* ap = (const ulonglong2*)&s_a[k][ng * 8];
            ulonglong2 a01 = ap[0];          // node pairs (+0,+1), (+2,+3)
            ulonglong2 a23 = ap[1];          // node pairs (+4,+5), (+6,+7)
            fma2(acc[0][0], a01.x, wd.x);  fma2(acc[0][1], a01.x, wd.y);
            fma2(acc[1][0], a01.y, wd.x);  fma2(acc[1][1], a01.y, wd.y);
            fma2(acc[2][0], a23.x, wd.x);  fma2(acc[2][1], a23.x, wd.y);
            fma2(acc[3][0], a23.y, wd.x);  fma2(acc[3][1], a23.y, wd.y);
        }
    }

    // ---- epilogue: relu + store (2 channels per node, float2) ----
    #pragma unroll
    for (int p = 0; p < 4; p++) {
        float l0, h0, l1, h1;
        upk(l0, h0, acc[p][0]);   // ch0   : even node / odd node
        upk(l1, h1, acc[p][1]);   // ch0+1 : even node / odd node
        int nd = m0 + ng * 8 + 2 * p;
        if (nd < n)
            *(float2*)&out[(size_t)nd * C + ch0] =
                make_float2(fmaxf(l0, 0.f), fmaxf(l1, 0.f));
        if (nd + 1 < n)
            *(float2*)&out[(size_t)(nd + 1) * C + ch0] =
                make_float2(fmaxf(h0, 0.f), fmaxf(h1, 0.f));
    }
}

// ---------------------------------------------------------------------------
extern "C" void kernel_launch(void* const* d_in, const int* in_sizes, int n_in,
                              void* d_out, int out_size) {
    const float* x  = (const float*)d_in[0];
    const int*   ei = (const int*)d_in[1];
    const float* w  = (const float*)d_in[2];
    const float* b  = (const float*)d_in[3];
    float*       out = (float*)d_out;

    int n = in_sizes[0] / C;     // 10000
    int e = in_sizes[1] / 2;     // 320000

    k_init<<<(K2 * C + 255) / 256, 256>>>(w, b, n);
    k_fill<<<(e + 255) / 256, 256>>>(ei, e, n);
    k_agg <<<(n * 32 + 255) / 256, 256>>>(x, n);

    dim3 grid((n + MT - 1) / MT, 2);
    k_gemm<<<grid, 128>>>(x, out, n);
}